// round 8
// baseline (speedup 1.0000x reference)
#include <cuda_runtime.h>

// Shapes fixed by the dataset:
//   x:                   [N_PTS,  N_NODES] float32
//   learned_edge_states: [N_CMP,  N_NODES] int32 (0 == EDG_NULL)
// Output: concat( new_comp_code [N_PTS,N_CMP] f32, premerge_idx [N_PTS,N_CMP] f32 )
#define N_PTS   256
#define N_NODES 1024
#define N_CMP   1024

#define THR  2.2f     // |x| filter threshold: E[count]=28.5, sd=5.2 for N(0,1)
#define CAP  64       // candidate capacity (P(count>64) ~ 1e-11)

typedef unsigned long long u64;

// Static device scratch (allocation-free rule).
__device__ unsigned d_maskT[N_NODES * (N_CMP / 32)];  // transposed mask bits
__device__ u64      d_top[N_PTS * 32];                // per-point top-32 keys
__device__ int      d_cnt[N_PTS];                     // per-point candidate count

// ---------------------------------------------------------------------------
// Kernel A: pack+transpose (reads edges only).
// ---------------------------------------------------------------------------
__global__ __launch_bounds__(256)
void pack_kernel(const int* __restrict__ edges) {
    const unsigned gw   = (blockIdx.x * blockDim.x + threadIdx.x) >> 5;
    const unsigned lane = threadIdx.x & 31;
    const unsigned q    = gw & 3;          // byte quarter (comps q*8..q*8+7)
    const unsigned cg   = (gw >> 2) & 31;  // component group
    const unsigned nch  = gw >> 7;         // node chunk
    const unsigned n    = nch * 32 + lane;

    unsigned B = 0;
    #pragma unroll
    for (int r = 0; r < 8; ++r) {
        int v = edges[(cg * 32 + q * 8 + r) * N_NODES + n];
        if (v) B |= 1u << r;
    }
    ((unsigned char*)d_maskT)[(n * 32 + cg) * 4 + q] = (unsigned char)B;
}

// ---------------------------------------------------------------------------
// Kernel B: per-point filter + single-warp top-32 sort (reads x only).
// Key: (bits(|x|) << 10) | (1023 - n) -> max key == max value, min index.
// ---------------------------------------------------------------------------
__device__ __forceinline__ u64 u64max(u64 a, u64 b) { return a > b ? a : b; }
__device__ __forceinline__ u64 u64min(u64 a, u64 b) { return a < b ? a : b; }

__global__ __launch_bounds__(512)
void topsel_kernel(const float* __restrict__ x) {
    __shared__ u64 s_cand[CAP];
    __shared__ int s_cnt;

    const int p    = blockIdx.x;
    const int t    = threadIdx.x;
    const int w    = t >> 5;
    const int lane = t & 31;

    if (t == 0) s_cnt = 0;
    __syncthreads();

    // filter: 2 consecutive elements per thread
    float2 xv = __ldg(&((const float2*)(x + p * N_NODES))[t]);
    #pragma unroll
    for (int e = 0; e < 2; ++e) {
        float    av   = fabsf(e == 0 ? xv.x : xv.y);
        int      n    = 2 * t + e;
        bool     pred = (av > THR);
        unsigned bal  = __ballot_sync(0xFFFFFFFFu, pred);
        int base = 0;
        if (lane == 0 && bal) base = atomicAdd(&s_cnt, __popc(bal));
        base = __shfl_sync(0xFFFFFFFFu, base, 0);
        if (pred) {
            int pos = base + __popc(bal & ((1u << lane) - 1u));
            if (pos < CAP) {
                s_cand[pos] = (((u64)__float_as_uint(av)) << 10)
                              | (unsigned)((N_NODES - 1) - n);
            }
        }
    }
    __syncthreads();

    const int cnt = s_cnt;
    if (w == 0) {
        // dual bitonic sort + merge -> top-32 descending (pads are key 0)
        u64 k1 = (lane      < cnt) ? s_cand[lane]      : 0ull;
        u64 k2 = (lane + 32 < cnt) ? s_cand[lane + 32] : 0ull;
        #pragma unroll
        for (int k = 2; k <= 32; k <<= 1) {
            #pragma unroll
            for (int j = k >> 1; j > 0; j >>= 1) {
                bool dirUp = ((lane & k) == 0);
                bool lower = ((lane & j) == 0);
                u64 o1 = __shfl_xor_sync(0xFFFFFFFFu, k1, j);
                u64 o2 = __shfl_xor_sync(0xFFFFFFFFu, k2, j);
                k1 = (dirUp == lower) ? u64min(k1, o1) : u64max(k1, o1);
                k2 = (dirUp == lower) ? u64min(k2, o2) : u64max(k2, o2);
            }
        }
        u64 a = __shfl_xor_sync(0xFFFFFFFFu, k1, 31);   // descending
        u64 m = u64max(a, k2);                          // bitonic top-32
        #pragma unroll
        for (int j = 16; j > 0; j >>= 1) {              // -> descending
            u64 o = __shfl_xor_sync(0xFFFFFFFFu, m, j);
            bool lower = ((lane & j) == 0);
            m = lower ? u64max(m, o) : u64min(m, o);
        }
        d_top[p * 32 + lane] = m;
        if (lane == 0) d_cnt[p] = cnt;
    }
}

// ---------------------------------------------------------------------------
// Kernel C: stage mask words for the top nodes + probe + store.
// ---------------------------------------------------------------------------
__device__ __forceinline__ void exact_scan(const float* __restrict__ x,
                                           int p, unsigned cg, unsigned bit,
                                           float& code, float& fidx) {
    u64 best = 0; bool has = false;
    for (int n = 0; n < N_NODES; ++n) {
        unsigned mw = __ldg(&d_maskT[(unsigned)n * 32 + cg]);
        if ((mw >> bit) & 1u) {
            float xn = __ldg(&x[p * N_NODES + n]);
            u64 k = (((u64)__float_as_uint(fabsf(xn))) << 10)
                    | (unsigned)((N_NODES - 1) - n);
            if (!has || k > best) { best = k; has = true; }
        }
    }
    if (has) {
        code = __uint_as_float((unsigned)(best >> 10));
        fidx = (float)((N_NODES - 1) - (int)(best & 1023ull));
    } else {
        code = 0.0f; fidx = 0.0f;
    }
}

__global__ __launch_bounds__(512)
void probe_kernel(const float* __restrict__ x,
                  float* __restrict__ out_code,
                  float* __restrict__ out_idx) {
    __shared__ u64      s_top[32];
    __shared__ unsigned s_w[32 * 32];     // rank-words per comp-group (4 KB)

    const int p    = blockIdx.x;
    const int t    = threadIdx.x;
    const int w    = t >> 5;
    const int lane = t & 31;

    const int  cnt = d_cnt[p];
    const bool ovf = (cnt > CAP);         // P ~ 1e-11

    if (!ovf) {
        // stage: lane kk loads top key + mask words for this warp's two cgs
        u64 keyl = __ldg(&d_top[p * 32 + lane]);
        if (w == 0) s_top[lane] = keyl;
        int nl = (N_NODES - 1) - (int)(keyl & 1023ull);
        s_w[w * 32 + lane]        = __ldg(&d_maskT[(unsigned)nl * 32 + (unsigned)w]);
        s_w[(w + 16) * 32 + lane] = __ldg(&d_maskT[(unsigned)nl * 32 + (unsigned)(w + 16)]);
        __syncthreads();

        const int n_valid = cnt < 32 ? cnt : 32;

        #pragma unroll
        for (int half = 0; half < 2; ++half) {
            const int      c   = t + half * 512;
            const unsigned cg  = (unsigned)c >> 5;     // warp-uniform
            const unsigned bit = (unsigned)c & 31;

            float code, fidx;
            bool found = false;
            for (int kk = 0; kk < n_valid; ++kk) {
                unsigned wrd = s_w[cg * 32 + kk];      // broadcast LDS
                if ((wrd >> bit) & 1u) {
                    u64 k3 = s_top[kk];
                    code = __uint_as_float((unsigned)(k3 >> 10));
                    fidx = (float)((N_NODES - 1) - (int)(k3 & 1023ull));
                    found = true;
                    break;
                }
            }
            if (!found) exact_scan(x, p, cg, bit, code, fidx);
            out_code[p * N_CMP + c] = code;
            out_idx [p * N_CMP + c] = fidx;
        }
    } else {
        #pragma unroll
        for (int half = 0; half < 2; ++half) {
            const int      c   = t + half * 512;
            const unsigned cg  = (unsigned)c >> 5;
            const unsigned bit = (unsigned)c & 31;
            float code, fidx;
            exact_scan(x, p, cg, bit, code, fidx);
            out_code[p * N_CMP + c] = code;
            out_idx [p * N_CMP + c] = fidx;
        }
    }
}

// ---------------------------------------------------------------------------
// Side stream + events, created once at static init (before graph capture;
// no device memory is allocated). Used to run pack ∥ topsel inside the graph.
// ---------------------------------------------------------------------------
struct HxStreams {
    cudaStream_t s2;
    cudaEvent_t  fork, join;
    HxStreams() {
        cudaStreamCreateWithFlags(&s2, cudaStreamNonBlocking);
        cudaEventCreateWithFlags(&fork, cudaEventDisableTiming);
        cudaEventCreateWithFlags(&join, cudaEventDisableTiming);
    }
};
static HxStreams g_hx;

extern "C" void kernel_launch(void* const* d_in, const int* in_sizes, int n_in,
                              void* d_out, int out_size) {
    const float* x     = (const float*)d_in[0];
    const int*   edges = (const int*)  d_in[1];
    float*       out   = (float*)d_out;

    // fork: pack on side stream, topsel on the capture stream (independent)
    cudaEventRecord(g_hx.fork, 0);
    cudaStreamWaitEvent(g_hx.s2, g_hx.fork, 0);
    pack_kernel<<<512, 256, 0, g_hx.s2>>>(edges);
    topsel_kernel<<<N_PTS, 512>>>(x);
    // join: probe needs both d_maskT and d_top
    cudaEventRecord(g_hx.join, g_hx.s2);
    cudaStreamWaitEvent(0, g_hx.join, 0);
    probe_kernel<<<N_PTS, 512>>>(x, out, out + (size_t)N_PTS * N_CMP);
}

// round 10
// speedup vs baseline: 1.4135x; 1.4135x over previous
#include <cuda_runtime.h>

// Shapes fixed by the dataset:
//   x:                   [N_PTS,  N_NODES] float32
//   learned_edge_states: [N_CMP,  N_NODES] int32 (0 == EDG_NULL)
// Output: concat( new_comp_code [N_PTS,N_CMP] f32, premerge_idx [N_PTS,N_CMP] f32 )
#define N_PTS   256
#define N_NODES 1024
#define N_CMP   1024

#define THR  2.2f     // |x| filter threshold: E[count]=28.5, sd=5.2 for N(0,1)
#define CAP  64       // candidate capacity (P(count>64) ~ 1e-11)

typedef unsigned long long u64;

// Mask bits, CG-MAJOR: d_maskT[cg*1024 + n] bit b == (edges[cg*32+b][n] != 0).
// 128 KB static scratch — L2-resident.
__device__ unsigned d_maskT[(N_CMP / 32) * N_NODES];

// ---------------------------------------------------------------------------
// Kernel 1: pack+transpose, ballot-free and scatter-free.
// Warp <-> (comp-group cg, 64-node chunk). Lane l owns nodes {2l, 2l+1}:
// iterate the 32 comp rows, accumulate transposed bits in registers, then one
// coalesced 256B warp store (uint2 per lane) into the cg-major layout.
// Reads: 32 independent warp-wide 256B loads (int2/lane), MLP=32.
// ---------------------------------------------------------------------------
__global__ __launch_bounds__(256)
void pack_kernel(const int* __restrict__ edges) {
    const unsigned gw   = (blockIdx.x * blockDim.x + threadIdx.x) >> 5;
    const unsigned lane = threadIdx.x & 31;
    const unsigned cg   = gw & 31;          // component group
    const unsigned nch  = gw >> 5;          // 64-node chunk (16 of them)

    const int2* e2 = (const int2*)edges;
    unsigned w0 = 0, w1 = 0;
    #pragma unroll
    for (int r = 0; r < 32; ++r) {
        int2 v = __ldg(&e2[(cg * 32 + r) * (N_NODES / 2) + nch * 32 + lane]);
        if (v.x) w0 |= 1u << r;
        if (v.y) w1 |= 1u << r;
    }
    // nodes n0 = nch*64 + 2*lane, n0+1 -> consecutive words in cg plane
    ((uint2*)d_maskT)[(cg * N_NODES + nch * 64) / 2 + lane] = make_uint2(w0, w1);
}

// ---------------------------------------------------------------------------
// Kernel 2 (fused): filter -> warp0 top-32 sort -> stage -> flat probe.
// Key: (bits(|x|) << 10) | (1023 - n) -> max key == max value, min index.
// ---------------------------------------------------------------------------
__device__ __forceinline__ u64 u64max(u64 a, u64 b) { return a > b ? a : b; }
__device__ __forceinline__ u64 u64min(u64 a, u64 b) { return a < b ? a : b; }

// Exact per-component scan (rare path; overflow / below-threshold / empty).
__device__ __forceinline__ void exact_scan(const float* __restrict__ x,
                                           int p, unsigned cg, unsigned bit,
                                           float& code, float& fidx) {
    u64 best = 0; bool has = false;
    for (int n = 0; n < N_NODES; ++n) {
        unsigned mw = __ldg(&d_maskT[cg * N_NODES + n]);
        if ((mw >> bit) & 1u) {
            float xn = __ldg(&x[p * N_NODES + n]);
            u64 k = (((u64)__float_as_uint(fabsf(xn))) << 10)
                    | (unsigned)((N_NODES - 1) - n);
            if (!has || k > best) { best = k; has = true; }
        }
    }
    if (has) {
        code = __uint_as_float((unsigned)(best >> 10));
        fidx = (float)((N_NODES - 1) - (int)(best & 1023ull));
    } else {
        code = 0.0f; fidx = 0.0f;
    }
}

__global__ __launch_bounds__(512)
void filter_probe_kernel(const float* __restrict__ x,
                         float* __restrict__ out_code,
                         float* __restrict__ out_idx) {
    __shared__ u64 s_cand[CAP];
    __shared__ u64 s_top[32];
    __shared__ __align__(16) unsigned s_w[32 * 32];  // rank-words per cg (4 KB)
    __shared__ int s_cnt;

    const int p    = blockIdx.x;
    const int t    = threadIdx.x;
    const int w    = t >> 5;
    const int lane = t & 31;

    if (t == 0) s_cnt = 0;
    __syncthreads();

    // ---- filter: 2 consecutive elements per thread ----
    float2 xv = __ldg(&((const float2*)(x + p * N_NODES))[t]);
    #pragma unroll
    for (int e = 0; e < 2; ++e) {
        float    av   = fabsf(e == 0 ? xv.x : xv.y);
        int      n    = 2 * t + e;
        bool     pred = (av > THR);
        unsigned bal  = __ballot_sync(0xFFFFFFFFu, pred);
        int base = 0;
        if (lane == 0 && bal) base = atomicAdd(&s_cnt, __popc(bal));
        base = __shfl_sync(0xFFFFFFFFu, base, 0);
        if (pred) {
            int pos = base + __popc(bal & ((1u << lane) - 1u));
            if (pos < CAP) {
                s_cand[pos] = (((u64)__float_as_uint(av)) << 10)
                              | (unsigned)((N_NODES - 1) - n);
            }
        }
    }
    __syncthreads();

    const int  cnt = s_cnt;
    const bool ovf = (cnt > CAP);        // block-uniform; P ~ 1e-11

    if (!ovf) {
        // ---- warp 0: dual bitonic sort + merge -> top-32 descending ----
        if (w == 0) {
            u64 k1 = (lane      < cnt) ? s_cand[lane]      : 0ull;
            u64 k2 = (lane + 32 < cnt) ? s_cand[lane + 32] : 0ull;
            #pragma unroll
            for (int k = 2; k <= 32; k <<= 1) {
                #pragma unroll
                for (int j = k >> 1; j > 0; j >>= 1) {
                    bool dirUp = ((lane & k) == 0);
                    bool lower = ((lane & j) == 0);
                    u64 o1 = __shfl_xor_sync(0xFFFFFFFFu, k1, j);
                    u64 o2 = __shfl_xor_sync(0xFFFFFFFFu, k2, j);
                    k1 = (dirUp == lower) ? u64min(k1, o1) : u64max(k1, o1);
                    k2 = (dirUp == lower) ? u64min(k2, o2) : u64max(k2, o2);
                }
            }
            u64 a = __shfl_xor_sync(0xFFFFFFFFu, k1, 31);   // descending
            u64 m = u64max(a, k2);                          // bitonic top-32
            #pragma unroll
            for (int j = 16; j > 0; j >>= 1) {              // -> descending
                u64 o = __shfl_xor_sync(0xFFFFFFFFu, m, j);
                bool lower = ((lane & j) == 0);
                m = lower ? u64max(m, o) : u64min(m, o);
            }
            s_top[lane] = m;
        }
        __syncthreads();

        const int n_valid = cnt < 32 ? cnt : 32;
        const unsigned vmask =
            (n_valid >= 32) ? 0xFFFFFFFFu : ((1u << n_valid) - 1u);

        // ---- stage: lane kk loads mask word for top-kk node, warp w serves
        //      comp-groups w and w+16 (cg-major layout) ----
        {
            u64 keyl = s_top[lane];
            int  nl  = (N_NODES - 1) - (int)(keyl & 1023ull);
            s_w[w * 32 + lane] =
                __ldg(&d_maskT[(unsigned)w * N_NODES + (unsigned)nl]);
            s_w[(w + 16) * 32 + lane] =
                __ldg(&d_maskT[(unsigned)(w + 16) * N_NODES + (unsigned)nl]);
        }
        __syncthreads();

        // ---- flat probe: build 32-bit hitmask from 8 broadcast uint4 LDS ----
        #pragma unroll
        for (int half = 0; half < 2; ++half) {
            const int      c   = t + half * 512;
            const unsigned cg  = (unsigned)c >> 5;     // warp-uniform
            const unsigned bit = (unsigned)c & 31;

            const uint4* row = (const uint4*)&s_w[cg * 32];
            unsigned hm = 0;
            #pragma unroll
            for (int q = 0; q < 8; ++q) {
                uint4 u = row[q];                      // broadcast LDS.128
                hm |= ((u.x >> bit) & 1u) << (4 * q + 0);
                hm |= ((u.y >> bit) & 1u) << (4 * q + 1);
                hm |= ((u.z >> bit) & 1u) << (4 * q + 2);
                hm |= ((u.w >> bit) & 1u) << (4 * q + 3);
            }
            hm &= vmask;

            float code, fidx;
            if (hm) {
                int kk = __ffs(hm) - 1;                // best rank with a hit
                u64 k3 = s_top[kk];
                code = __uint_as_float((unsigned)(k3 >> 10));
                fidx = (float)((N_NODES - 1) - (int)(k3 & 1023ull));
            } else {
                // masked max below THR (P~1e-9/comp) or empty comp
                exact_scan(x, p, cg, bit, code, fidx);
            }
            out_code[p * N_CMP + c] = code;
            out_idx [p * N_CMP + c] = fidx;
        }
    } else {
        // overflow: exact path for every comp this thread owns
        #pragma unroll
        for (int half = 0; half < 2; ++half) {
            const int      c   = t + half * 512;
            const unsigned cg  = (unsigned)c >> 5;
            const unsigned bit = (unsigned)c & 31;
            float code, fidx;
            exact_scan(x, p, cg, bit, code, fidx);
            out_code[p * N_CMP + c] = code;
            out_idx [p * N_CMP + c] = fidx;
        }
    }
}

// ---------------------------------------------------------------------------
extern "C" void kernel_launch(void* const* d_in, const int* in_sizes, int n_in,
                              void* d_out, int out_size) {
    const float* x     = (const float*)d_in[0];
    const int*   edges = (const int*)  d_in[1];
    float*       out   = (float*)d_out;

    // 512 warps: 64 blocks x 256 threads (32 cg * 16 node-chunks)
    pack_kernel<<<64, 256>>>(edges);
    filter_probe_kernel<<<N_PTS, 512>>>(x, out, out + (size_t)N_PTS * N_CMP);
}